// round 10
// baseline (speedup 1.0000x reference)
#include <cuda_runtime.h>
#include <cuda_bf16.h>
#include <cstdint>

#define BB 8
#define CC 192
#define CQ 32
#define NN 16384
#define TILE 64
#define NT (NN / TILE)      // 256 tiles
#define NGRP 16             // tile-groups per batch (fused kernel)
#define TPG (NT / NGRP)     // 16 tiles per group
#define KXW 200             // KX row width (192 cols + ksum col 192 + pad)

// ---------------- scratch (static device globals; no allocations) ----------------
__device__ float g_Qn[(size_t)BB * NN * CQ];              // [b][n][r]
__device__ float g_KXPart[(size_t)BB * NGRP * 33 * KXW];  // per-group KX partials
__device__ float g_KX[BB * 33 * KXW];
__device__ float g_Mat[BB * CQ * CC];
__device__ float g_Vsum[BB * CC];
__device__ float g_KsumE[BB * CQ];                        // Ksum + EPS

// ---------------- warp MMA helpers (baseline PTX, sm_80+) ----------------
__device__ __forceinline__ uint32_t s2u(const void* p) {
    uint32_t a;
    asm("{ .reg .u64 t; cvta.to.shared.u64 t, %1; cvt.u32.u64 %0, t; }" : "=r"(a) : "l"(p));
    return a;
}
__device__ __forceinline__ void ldm4(uint32_t* r, uint32_t a) {
    asm volatile("ldmatrix.sync.aligned.m8n8.x4.shared.b16 {%0,%1,%2,%3}, [%4];"
                 : "=r"(r[0]), "=r"(r[1]), "=r"(r[2]), "=r"(r[3]) : "r"(a));
}
__device__ __forceinline__ void ldm2(uint32_t* r, uint32_t a) {
    asm volatile("ldmatrix.sync.aligned.m8n8.x2.shared.b16 {%0,%1}, [%2];"
                 : "=r"(r[0]), "=r"(r[1]) : "r"(a));
}
__device__ __forceinline__ void ldm2t(uint32_t* r, uint32_t a) {
    asm volatile("ldmatrix.sync.aligned.m8n8.x2.trans.shared.b16 {%0,%1}, [%2];"
                 : "=r"(r[0]), "=r"(r[1]) : "r"(a));
}
__device__ __forceinline__ void mma16816(float* d, const uint32_t* a, const uint32_t* b) {
    asm volatile("mma.sync.aligned.m16n8k16.row.col.f32.bf16.bf16.f32 "
                 "{%0,%1,%2,%3},{%4,%5,%6,%7},{%8,%9},{%0,%1,%2,%3};"
                 : "+f"(d[0]), "+f"(d[1]), "+f"(d[2]), "+f"(d[3])
                 : "r"(a[0]), "r"(a[1]), "r"(a[2]), "r"(a[3]), "r"(b[0]), "r"(b[1]));
}
__device__ __forceinline__ uint32_t bpack2(float a, float b) {
    __nv_bfloat162 t = __floats2bfloat162_rn(a, b);
    return *(uint32_t*)&t;
}
__device__ __forceinline__ float bhi(float v) {
    return __bfloat162float(__float2bfloat16(v));
}
__device__ __forceinline__ void bsplit(float v, uint16_t& h, uint16_t& l) {
    __nv_bfloat16 hb = __float2bfloat16(v);
    __nv_bfloat16 lb = __float2bfloat16(v - __bfloat162float(hb));
    h = *(uint16_t*)&hb;
    l = *(uint16_t*)&lb;
}
__device__ __forceinline__ float bf16u(uint16_t u) {
    __nv_bfloat16 t = *(__nv_bfloat16*)&u;
    return __bfloat162float(t);
}
__device__ __forceinline__ void bsplit4(float4 v, uint32_t* h2, uint32_t* l2) {
    float hx = bhi(v.x), hy = bhi(v.y), hz = bhi(v.z), hw = bhi(v.w);
    h2[0] = bpack2(v.x, v.y);
    h2[1] = bpack2(v.z, v.w);
    l2[0] = bpack2(v.x - hx, v.y - hy);
    l2[1] = bpack2(v.z - hz, v.w - hw);
}

// ---------------- fused kernel: QK proj + norm + Qn + (Kn_pad·x^T accumulated over 16 tiles) ----------------
// smem (bytes)
#define FQ_WH 0            // Wqk hi [64 o][200 c]
#define FQ_WL 25600        // Wqk lo
#define FQ_XH 51200        // X hi [200 rows][72 j]  (x1 then x; rows 192-199 static ones/zero)
#define FQ_XL 80000        // X lo
#define FQ_ST 108800       // staging f32 [64 o][72 j]
#define FQ_KH 127232       // Kn_pad hi [48 m][72 j]
#define FQ_KL 134144       // Kn_pad lo
#define FQ_B  141056       // biases f32 [64]
#define FQ_NRM 141312      // norms f32 [128]
#define FQ_TOT 141824

__global__ __launch_bounds__(256) void fused_qkx_kernel(
    const float* __restrict__ x, const float* __restrict__ x1,
    const float* __restrict__ Wq, const float* __restrict__ bq,
    const float* __restrict__ Wk, const float* __restrict__ bk)
{
    extern __shared__ char sm[];
    const uint32_t sb = s2u(sm);
    const int tid = threadIdx.x;
    const int lane = tid & 31;
    const int wid = tid >> 5;
    const int ln16 = lane & 15;
    const int b = blockIdx.y;
    const int grp = blockIdx.x;

    float* sB = (float*)(sm + FQ_B);
    if (tid < 64) sB[tid] = (tid < CQ) ? bq[tid] : bk[tid - CQ];

    // W hi/lo (once per CTA), stride 200
    for (int i = tid; i < 64 * 48; i += 256) {
        int o = i / 48, c4 = (i % 48) * 4;
        float4 v = (o < CQ) ? *(const float4*)(Wq + o * CC + c4)
                            : *(const float4*)(Wk + (o - CQ) * CC + c4);
        uint32_t h2[2], l2[2];
        bsplit4(v, h2, l2);
        *(uint32_t*)(sm + FQ_WH + (o * 200 + c4) * 2)     = h2[0];
        *(uint32_t*)(sm + FQ_WH + (o * 200 + c4 + 2) * 2) = h2[1];
        *(uint32_t*)(sm + FQ_WL + (o * 200 + c4) * 2)     = l2[0];
        *(uint32_t*)(sm + FQ_WL + (o * 200 + c4 + 2) * 2) = l2[1];
    }
    // static X rows 192-199: row 192 = ones (ksum channel), 193-199 = zero
    for (int i = tid; i < 8 * 36; i += 256) {
        int r = 192 + i / 36, jc = i % 36;
        uint32_t hv = (r == 192 && jc < 32) ? 0x3F803F80u : 0u;
        *(uint32_t*)(sm + FQ_XH + (r * 72) * 2 + jc * 4) = hv;
        *(uint32_t*)(sm + FQ_XL + (r * 72) * 2 + jc * 4) = 0u;
    }
    // static Kn_pad rows 32-47: row 32 = ones (xsum row), 33-47 = zero
    for (int i = tid; i < 16 * 36; i += 256) {
        int r = 32 + i / 36, jc = i % 36;
        uint32_t hv = (r == 32 && jc < 32) ? 0x3F803F80u : 0u;
        *(uint32_t*)(sm + FQ_KH + (r * 72) * 2 + jc * 4) = hv;
        *(uint32_t*)(sm + FQ_KL + (r * 72) * 2 + jc * 4) = 0u;
    }

    // persistent KX accumulators (warp 7 carries 4th n-tile = cols 192-199)
    const int ntl = (wid == 7) ? 4 : 3;
    const int n0w = wid * 24;
    float dkx[3][4][4];
    #pragma unroll
    for (int mt = 0; mt < 3; mt++)
        #pragma unroll
        for (int nt = 0; nt < 4; nt++)
            #pragma unroll
            for (int e = 0; e < 4; e++) dkx[mt][nt][e] = 0.f;

    const int wm = wid & 1, wn = wid >> 1;   // QK warp grid

    for (int t = 0; t < TPG; t++) {
        const int n0 = (grp * TPG + t) * TILE;
        __syncthreads();   // prior kx-MMA reads of X done (t=0: static init done)

        // x1 tile -> X rows 0-191
        const float* xb1 = x1 + (size_t)b * CC * NN + n0;
        for (int i = tid; i < CC * 16; i += 256) {
            int c = i >> 4, j4 = (i & 15) * 4;
            float4 v = *(const float4*)(xb1 + (size_t)c * NN + j4);
            uint32_t h2[2], l2[2];
            bsplit4(v, h2, l2);
            *(uint32_t*)(sm + FQ_XH + (c * 72 + j4) * 2)     = h2[0];
            *(uint32_t*)(sm + FQ_XH + (c * 72 + j4 + 2) * 2) = h2[1];
            *(uint32_t*)(sm + FQ_XL + (c * 72 + j4) * 2)     = l2[0];
            *(uint32_t*)(sm + FQ_XL + (c * 72 + j4 + 2) * 2) = l2[1];
        }
        __syncthreads();

        // QK MMA: D[o:64][j:64] = Wqk · X1, K=192
        float d[2][2][4];
        #pragma unroll
        for (int mt = 0; mt < 2; mt++)
            #pragma unroll
            for (int nt = 0; nt < 2; nt++)
                #pragma unroll
                for (int e = 0; e < 4; e++) d[mt][nt][e] = 0.f;

        #pragma unroll
        for (int ks = 0; ks < 12; ks++) {
            uint32_t ah[2][4], al[2][4];
            const int acol = ks * 16 + (lane >> 4) * 8;
            #pragma unroll
            for (int mt = 0; mt < 2; mt++) {
                uint32_t off = (uint32_t)(((wm * 32 + mt * 16 + ln16) * 200 + acol) * 2);
                ldm4(ah[mt], sb + FQ_WH + off);
                ldm4(al[mt], sb + FQ_WL + off);
            }
            uint32_t bh[2][2], bl[2][2];
            const int brow = ks * 16 + ln16;
            #pragma unroll
            for (int nt = 0; nt < 2; nt++) {
                uint32_t off = (uint32_t)((brow * 72 + wn * 16 + nt * 8) * 2);
                ldm2t(bh[nt], sb + FQ_XH + off);
                ldm2t(bl[nt], sb + FQ_XL + off);
            }
            #pragma unroll
            for (int mt = 0; mt < 2; mt++)
                #pragma unroll
                for (int nt = 0; nt < 2; nt++) {
                    mma16816(d[mt][nt], ah[mt], bh[nt]);
                    mma16816(d[mt][nt], ah[mt], bl[nt]);
                    mma16816(d[mt][nt], al[mt], bh[nt]);
                }
        }
        __syncthreads();   // MMA reads of X done -> X may be overwritten

        // stage D+bias -> sST ; concurrently load x tile -> X rows 0-191 (disjoint regions)
        float* sST = (float*)(sm + FQ_ST);
        #pragma unroll
        for (int mt = 0; mt < 2; mt++) {
            const int o0 = wm * 32 + mt * 16 + (lane >> 2);
            #pragma unroll
            for (int nt = 0; nt < 2; nt++) {
                const int j0 = wn * 16 + nt * 8 + (lane & 3) * 2;
                #pragma unroll
                for (int rr = 0; rr < 2; rr++) {
                    const int o = o0 + rr * 8;
                    sST[o * 72 + j0]     = d[mt][nt][rr * 2 + 0] + sB[o];
                    sST[o * 72 + j0 + 1] = d[mt][nt][rr * 2 + 1] + sB[o];
                }
            }
        }
        const float* xb = x + (size_t)b * CC * NN + n0;
        for (int i = tid; i < CC * 16; i += 256) {
            int c = i >> 4, j4 = (i & 15) * 4;
            float4 v = *(const float4*)(xb + (size_t)c * NN + j4);
            uint32_t h2[2], l2[2];
            bsplit4(v, h2, l2);
            *(uint32_t*)(sm + FQ_XH + (c * 72 + j4) * 2)     = h2[0];
            *(uint32_t*)(sm + FQ_XH + (c * 72 + j4 + 2) * 2) = h2[1];
            *(uint32_t*)(sm + FQ_XL + (c * 72 + j4) * 2)     = l2[0];
            *(uint32_t*)(sm + FQ_XL + (c * 72 + j4 + 2) * 2) = l2[1];
        }
        __syncthreads();

        // norms
        float* sNrm = (float*)(sm + FQ_NRM);
        if (tid < 128) {
            int j = tid & 63, h = tid >> 6;
            float s = 0.f;
            #pragma unroll
            for (int r = 0; r < CQ; r++) {
                float v = sST[(h * CQ + r) * 72 + j];
                s += v * v;
            }
            sNrm[tid] = rsqrtf(s);
        }
        __syncthreads();

        // Qn -> global ; Kn split -> Kn_pad rows 0-31
        float* gq = g_Qn + (size_t)(b * NN + n0) * CQ;
        for (int i = tid; i < CQ * TILE; i += 256) {
            int j = i >> 5, r = i & 31;
            gq[i] = sST[r * 72 + j] * sNrm[j];
        }
        for (int i = tid; i < CQ * TILE; i += 256) {
            int m = i >> 6, j = i & 63;
            float v = sST[(CQ + m) * 72 + j] * sNrm[64 + j];
            uint16_t h, l; bsplit(v, h, l);
            *(uint16_t*)(sm + FQ_KH + (m * 72 + j) * 2) = h;
            *(uint16_t*)(sm + FQ_KL + (m * 72 + j) * 2) = l;
        }
        __syncthreads();

        // KX MMA accumulate: D[m:48][c:200] += Kn_pad · x^T (K = 64)
        #pragma unroll
        for (int ks = 0; ks < 4; ks++) {
            uint32_t ah[3][4], al[3][4];
            const int acol = ks * 16 + (lane >> 4) * 8;
            #pragma unroll
            for (int mt = 0; mt < 3; mt++) {
                uint32_t off = (uint32_t)(((mt * 16 + ln16) * 72 + acol) * 2);
                ldm4(ah[mt], sb + FQ_KH + off);
                ldm4(al[mt], sb + FQ_KL + off);
            }
            uint32_t bh[4][2], bl[4][2];
            for (int nt = 0; nt < ntl; nt++) {
                const int crow = n0w + nt * 8 + (lane & 7);
                const int kcol = ks * 16 + ((lane >> 3) & 1) * 8;
                uint32_t off = (uint32_t)((crow * 72 + kcol) * 2);
                ldm2(bh[nt], sb + FQ_XH + off);
                ldm2(bl[nt], sb + FQ_XL + off);
            }
            #pragma unroll
            for (int mt = 0; mt < 3; mt++) {
                for (int nt = 0; nt < ntl; nt++) {
                    mma16816(dkx[mt][nt], ah[mt], bh[nt]);
                    mma16816(dkx[mt][nt], ah[mt], bl[nt]);
                    mma16816(dkx[mt][nt], al[mt], bh[nt]);
                }
            }
        }   // ks
    }       // t (tile loop)

    // write KX partials [33][200] (row 32 = xsum; col 192 = ksum)
    float* kxp = g_KXPart + (size_t)(b * NGRP + grp) * (33 * KXW);
    #pragma unroll
    for (int mt = 0; mt < 3; mt++) {
        const int r0 = mt * 16 + (lane >> 2);
        for (int nt = 0; nt < ntl; nt++) {
            const int c0 = n0w + nt * 8 + (lane & 3) * 2;
            #pragma unroll
            for (int rr = 0; rr < 2; rr++) {
                const int r = r0 + rr * 8;
                if (r < 33) {
                    kxp[r * KXW + c0]     = dkx[mt][nt][rr * 2 + 0];
                    kxp[r * KXW + c0 + 1] = dkx[mt][nt][rr * 2 + 1];
                }
            }
        }
    }
}

// ---------------- reduce KX partials; emit KsumE ----------------
__global__ __launch_bounds__(256) void kxred_kernel()
{
    const int b = blockIdx.y;
    const int i = blockIdx.x * 256 + threadIdx.x;
    if (i >= 33 * KXW) return;
    const float* p = g_KXPart + (size_t)b * NGRP * (33 * KXW) + i;
    float s = 0.f;
    #pragma unroll
    for (int t = 0; t < NGRP; t++) s += p[(size_t)t * (33 * KXW)];
    g_KX[b * 33 * KXW + i] = s;
    int r = i / KXW, c = i - r * KXW;
    if (c == 192 && r < CQ) g_KsumE[b * CQ + r] = s + 1e-6f;
}

// ---------------- tiny fp32 contraction: Mat = KX·Wv^T + Ksum·bv^T ; Vsum = Wv·xsum + N·bv ----------------
#define MS_KX 0                      // [33][193] f32
#define MS_W  25476                  // [32][193] f32
#define MS_TOT 50180

__global__ __launch_bounds__(256) void matsmall_kernel(
    const float* __restrict__ Wv, const float* __restrict__ bv)
{
    extern __shared__ char sm[];
    float* sKX = (float*)(sm + MS_KX);
    float* sW  = (float*)(sm + MS_W);
    const int tid = threadIdx.x;
    const int b = blockIdx.y;
    const int c0 = blockIdx.x * 32;

    for (int i = tid; i < 33 * CC; i += 256) {
        int r = i / CC, k = i - r * CC;
        sKX[r * 193 + k] = g_KX[b * 33 * KXW + r * KXW + k];
    }
    for (int i = tid; i < 32 * CC; i += 256) {
        int cl = i / CC, k = i - cl * CC;
        sW[cl * 193 + k] = Wv[(c0 + cl) * CC + k];
    }
    __syncthreads();

    const int m = tid >> 3, clb = (tid & 7) * 4;
    float acc[4] = {0.f, 0.f, 0.f, 0.f};
    for (int k = 0; k < CC; k++) {
        float kx = sKX[m * 193 + k];
        #pragma unroll
        for (int q = 0; q < 4; q++) acc[q] += kx * sW[(clb + q) * 193 + k];
    }
    const float ks = g_KX[b * 33 * KXW + m * KXW + 192];   // Ksum
    #pragma unroll
    for (int q = 0; q < 4; q++) {
        int c = c0 + clb + q;
        g_Mat[b * CQ * CC + m * CC + c] = acc[q] + ks * bv[c];
    }

    if (tid < 32) {
        float vs = 0.f;
        for (int k = 0; k < CC; k++) vs += sW[tid * 193 + k] * sKX[32 * 193 + k];
        int c = c0 + tid;
        g_Vsum[b * CC + c] = vs + (float)NN * bv[c];
    }
}

// ---------------- epilogue via mma.sync (R7-proven; float4 output path) ----------------
#define SF_AH 0
#define SF_AL 5120
#define SF_BH 10240
#define SF_BL 23040
#define SF_ST 35840
#define SF_VS 91136
#define SF_KS 91904
#define SF_TL 92032
#define SF_TOT 92288

__global__ __launch_bounds__(256) void final_mma_kernel(
    const float* __restrict__ gamma, float* __restrict__ out)
{
    extern __shared__ char sm[];
    const uint32_t sb = s2u(sm);
    const int tid = threadIdx.x;
    const int lane = tid & 31;
    const int wid = tid >> 5;
    const int ln16 = lane & 15;
    const int b = blockIdx.y;
    const int n0 = blockIdx.x * TILE;

    const float* gq = g_Qn + (size_t)(b * NN + n0) * CQ;
    for (int i = tid; i < TILE * CQ; i += 256) {
        int j = i >> 5, r = i & 31;
        float v = gq[i];
        uint16_t h, l; bsplit(v, h, l);
        *(uint16_t*)(sm + SF_AH + (j * 40 + r) * 2) = h;
        *(uint16_t*)(sm + SF_AL + (j * 40 + r) * 2) = l;
    }
    for (int i = tid; i < CQ * CC; i += 256) {
        int r = i / CC, c = i - r * CC;
        float v = g_Mat[b * CQ * CC + i];
        uint16_t h, l; bsplit(v, h, l);
        *(uint16_t*)(sm + SF_BH + (r * 200 + c) * 2) = h;
        *(uint16_t*)(sm + SF_BL + (r * 200 + c) * 2) = l;
    }
    float* sVS = (float*)(sm + SF_VS);
    float* sKS = (float*)(sm + SF_KS);
    float* sTL = (float*)(sm + SF_TL);
    if (tid < CC) sVS[tid] = g_Vsum[b * CC + tid];
    if (tid < CQ) sKS[tid] = g_KsumE[b * CQ + tid];
    __syncthreads();

    if (tid < TILE) {
        float s = 0.f;
        #pragma unroll
        for (int r = 0; r < CQ; r++) {
            float q = bf16u(*(uint16_t*)(sm + SF_AH + (tid * 40 + r) * 2))
                    + bf16u(*(uint16_t*)(sm + SF_AL + (tid * 40 + r) * 2));
            s += q * sKS[r];
        }
        sTL[tid] = 1.0f / ((float)NN + s);
    }

    const int wm = wid & 1, wn = wid >> 1;
    float d[2][6][4];
    #pragma unroll
    for (int mt = 0; mt < 2; mt++)
        #pragma unroll
        for (int nt = 0; nt < 6; nt++)
            #pragma unroll
            for (int e = 0; e < 4; e++) d[mt][nt][e] = 0.f;

    #pragma unroll
    for (int ks = 0; ks < 2; ks++) {
        uint32_t ah[2][4], al[2][4];
        const int acol = ks * 16 + (lane >> 4) * 8;
        #pragma unroll
        for (int mt = 0; mt < 2; mt++) {
            uint32_t off = (uint32_t)(((wm * 32 + mt * 16 + ln16) * 40 + acol) * 2);
            ldm4(ah[mt], sb + SF_AH + off);
            ldm4(al[mt], sb + SF_AL + off);
        }
        uint32_t bh[6][2], bl[6][2];
        const int brow = ks * 16 + ln16;
        #pragma unroll
        for (int nt = 0; nt < 6; nt++) {
            uint32_t off = (uint32_t)((brow * 200 + wn * 48 + nt * 8) * 2);
            ldm2t(bh[nt], sb + SF_BH + off);
            ldm2t(bl[nt], sb + SF_BL + off);
        }
        #pragma unroll
        for (int mt = 0; mt < 2; mt++)
            #pragma unroll
            for (int nt = 0; nt < 6; nt++) {
                mma16816(d[mt][nt], ah[mt], bh[nt]);
                mma16816(d[mt][nt], ah[mt], bl[nt]);
                mma16816(d[mt][nt], al[mt], bh[nt]);
            }
    }

    float* sST = (float*)(sm + SF_ST);   // [192][72]
    #pragma unroll
    for (int mt = 0; mt < 2; mt++) {
        const int j0 = wm * 32 + mt * 16 + (lane >> 2);
        #pragma unroll
        for (int nt = 0; nt < 6; nt++) {
            const int c0 = wn * 48 + nt * 8 + (lane & 3) * 2;
            #pragma unroll
            for (int rr = 0; rr < 2; rr++) {
                const int j = j0 + rr * 8;
                sST[(c0)     * 72 + j] = d[mt][nt][rr * 2 + 0];
                sST[(c0 + 1) * 72 + j] = d[mt][nt][rr * 2 + 1];
            }
        }
    }
    __syncthreads();

    const float g = gamma[0];
    float* ob = out + (size_t)b * CC * NN + n0;
    for (int i = tid; i < CC * 16; i += 256) {
        int c = i >> 4, j4 = (i & 15) * 4;
        float4 s4 = *(const float4*)(sST + c * 72 + j4);
        float4 t4 = *(const float4*)(sTL + j4);
        float vs = sVS[c];
        float4 o4;
        o4.x = (vs + s4.x) * t4.x * g;
        o4.y = (vs + s4.y) * t4.y * g;
        o4.z = (vs + s4.z) * t4.z * g;
        o4.w = (vs + s4.w) * t4.w * g;
        *(float4*)(ob + (size_t)c * NN + j4) = o4;
    }
}

// ---------------- launch ----------------
extern "C" void kernel_launch(void* const* d_in, const int* in_sizes, int n_in,
                              void* d_out, int out_size)
{
    const float* x  = (const float*)d_in[0];
    const float* x1 = (const float*)d_in[1];
    const float* Wq = (const float*)d_in[2];
    const float* bq = (const float*)d_in[3];
    const float* Wk = (const float*)d_in[4];
    const float* bk = (const float*)d_in[5];
    const float* Wv = (const float*)d_in[6];
    const float* bv = (const float*)d_in[7];
    const float* gm = (const float*)d_in[8];
    float* out = (float*)d_out;

    cudaFuncSetAttribute(fused_qkx_kernel, cudaFuncAttributeMaxDynamicSharedMemorySize, FQ_TOT);
    cudaFuncSetAttribute(matsmall_kernel,  cudaFuncAttributeMaxDynamicSharedMemorySize, MS_TOT);
    cudaFuncSetAttribute(final_mma_kernel, cudaFuncAttributeMaxDynamicSharedMemorySize, SF_TOT);

    fused_qkx_kernel<<<dim3(NGRP, BB), 256, FQ_TOT>>>(x, x1, Wq, bq, Wk, bk);
    kxred_kernel<<<dim3((33 * KXW + 255) / 256, BB), 256>>>();
    matsmall_kernel<<<dim3(6, BB), 256, MS_TOT>>>(Wv, bv);
    final_mma_kernel<<<dim3(NT, BB), 256, SF_TOT>>>(gm, out);
}

// round 11
// speedup vs baseline: 1.3833x; 1.3833x over previous
#include <cuda_runtime.h>
#include <cuda_bf16.h>
#include <cstdint>

#define BB 8
#define CC 192
#define CQ 32
#define NN 16384
#define TILE 64
#define NT (NN / TILE)      // 256 tiles (qk / final)
#define TKX 128
#define NTK (NN / TKX)      // 128 tiles (kx)
#define FTPC 4              // final: tiles per CTA

// ---------------- scratch (static device globals; no allocations) ----------------
__device__ float g_Qn[(size_t)BB * NN * CQ];            // [b][n][r]
__device__ float g_Kn[(size_t)BB * CQ * NN];            // [b][r][n]
__device__ float g_KXPart[(size_t)BB * NTK * 33 * CC];  // per-tile KX partials (+xsum row)
__device__ float g_KX[BB * 33 * CC];
__device__ uint16_t g_MatH[BB * CQ * CC];               // pre-split Mat (bf16 hi/lo)
__device__ uint16_t g_MatL[BB * CQ * CC];
__device__ float g_Vsum[BB * CC];
__device__ float g_Ksum[BB * CQ];                       // plain
__device__ float g_KsumE[BB * CQ];                      // + EPS

// ---------------- warp MMA helpers (baseline PTX, sm_80+) ----------------
__device__ __forceinline__ uint32_t s2u(const void* p) {
    uint32_t a;
    asm("{ .reg .u64 t; cvta.to.shared.u64 t, %1; cvt.u32.u64 %0, t; }" : "=r"(a) : "l"(p));
    return a;
}
__device__ __forceinline__ void ldm4(uint32_t* r, uint32_t a) {
    asm volatile("ldmatrix.sync.aligned.m8n8.x4.shared.b16 {%0,%1,%2,%3}, [%4];"
                 : "=r"(r[0]), "=r"(r[1]), "=r"(r[2]), "=r"(r[3]) : "r"(a));
}
__device__ __forceinline__ void ldm2(uint32_t* r, uint32_t a) {
    asm volatile("ldmatrix.sync.aligned.m8n8.x2.shared.b16 {%0,%1}, [%2];"
                 : "=r"(r[0]), "=r"(r[1]) : "r"(a));
}
__device__ __forceinline__ void ldm2t(uint32_t* r, uint32_t a) {
    asm volatile("ldmatrix.sync.aligned.m8n8.x2.trans.shared.b16 {%0,%1}, [%2];"
                 : "=r"(r[0]), "=r"(r[1]) : "r"(a));
}
__device__ __forceinline__ void mma16816(float* d, const uint32_t* a, const uint32_t* b) {
    asm volatile("mma.sync.aligned.m16n8k16.row.col.f32.bf16.bf16.f32 "
                 "{%0,%1,%2,%3},{%4,%5,%6,%7},{%8,%9},{%0,%1,%2,%3};"
                 : "+f"(d[0]), "+f"(d[1]), "+f"(d[2]), "+f"(d[3])
                 : "r"(a[0]), "r"(a[1]), "r"(a[2]), "r"(a[3]), "r"(b[0]), "r"(b[1]));
}
__device__ __forceinline__ uint32_t bpack2(float a, float b) {
    __nv_bfloat162 t = __floats2bfloat162_rn(a, b);
    return *(uint32_t*)&t;
}
__device__ __forceinline__ float bhi(float v) {
    return __bfloat162float(__float2bfloat16(v));
}
__device__ __forceinline__ void bsplit(float v, uint16_t& h, uint16_t& l) {
    __nv_bfloat16 hb = __float2bfloat16(v);
    __nv_bfloat16 lb = __float2bfloat16(v - __bfloat162float(hb));
    h = *(uint16_t*)&hb;
    l = *(uint16_t*)&lb;
}
__device__ __forceinline__ float bf16u(uint16_t u) {
    __nv_bfloat16 t = *(__nv_bfloat16*)&u;
    return __bfloat162float(t);
}
__device__ __forceinline__ void bsplit4(float4 v, uint32_t* h2, uint32_t* l2) {
    float hx = bhi(v.x), hy = bhi(v.y), hz = bhi(v.z), hw = bhi(v.w);
    h2[0] = bpack2(v.x, v.y);
    h2[1] = bpack2(v.z, v.w);
    l2[0] = bpack2(v.x - hx, v.y - hy);
    l2[1] = bpack2(v.z - hz, v.w - hw);
}

// ---------------- kernel 1: Q,K projection via mma.sync + per-column L2 norm (R7 proven) ----------------
#define SQ_XH 0
#define SQ_XL 27648
#define SQ_WH 55296
#define SQ_WL 80896
#define SQ_ST 55296
#define SQ_B  106496
#define SQ_NRM 106752
#define SQ_TOT 107264

__global__ __launch_bounds__(256) void qk_mma_kernel(
    const float* __restrict__ x1, const float* __restrict__ Wq,
    const float* __restrict__ bq, const float* __restrict__ Wk,
    const float* __restrict__ bk)
{
    extern __shared__ char sm[];
    const uint32_t sb = s2u(sm);
    const int tid = threadIdx.x;
    const int lane = tid & 31;
    const int wid = tid >> 5;
    const int ln16 = lane & 15;
    const int b = blockIdx.y;
    const int n0 = blockIdx.x * TILE;

    float* sB = (float*)(sm + SQ_B);
    if (tid < 64) sB[tid] = (tid < CQ) ? bq[tid] : bk[tid - CQ];

    const float* xb = x1 + (size_t)b * CC * NN + n0;
    for (int i = tid; i < CC * 16; i += 256) {
        int c = i >> 4, j4 = (i & 15) * 4;
        float4 v = *(const float4*)(xb + (size_t)c * NN + j4);
        uint32_t h2[2], l2[2];
        bsplit4(v, h2, l2);
        *(uint32_t*)(sm + SQ_XH + (c * 72 + j4) * 2)     = h2[0];
        *(uint32_t*)(sm + SQ_XH + (c * 72 + j4 + 2) * 2) = h2[1];
        *(uint32_t*)(sm + SQ_XL + (c * 72 + j4) * 2)     = l2[0];
        *(uint32_t*)(sm + SQ_XL + (c * 72 + j4 + 2) * 2) = l2[1];
    }
    for (int i = tid; i < 64 * 48; i += 256) {
        int o = i / 48, c4 = (i % 48) * 4;
        float4 v = (o < CQ) ? *(const float4*)(Wq + o * CC + c4)
                            : *(const float4*)(Wk + (o - CQ) * CC + c4);
        uint32_t h2[2], l2[2];
        bsplit4(v, h2, l2);
        *(uint32_t*)(sm + SQ_WH + (o * 200 + c4) * 2)     = h2[0];
        *(uint32_t*)(sm + SQ_WH + (o * 200 + c4 + 2) * 2) = h2[1];
        *(uint32_t*)(sm + SQ_WL + (o * 200 + c4) * 2)     = l2[0];
        *(uint32_t*)(sm + SQ_WL + (o * 200 + c4 + 2) * 2) = l2[1];
    }
    __syncthreads();

    const int wm = wid & 1, wn = wid >> 1;
    float d[2][2][4];
    #pragma unroll
    for (int mt = 0; mt < 2; mt++)
        #pragma unroll
        for (int nt = 0; nt < 2; nt++)
            #pragma unroll
            for (int e = 0; e < 4; e++) d[mt][nt][e] = 0.f;

    #pragma unroll
    for (int ks = 0; ks < 12; ks++) {
        uint32_t ah[2][4], al[2][4];
        const int acol = ks * 16 + (lane >> 4) * 8;
        #pragma unroll
        for (int mt = 0; mt < 2; mt++) {
            uint32_t off = (uint32_t)(((wm * 32 + mt * 16 + ln16) * 200 + acol) * 2);
            ldm4(ah[mt], sb + SQ_WH + off);
            ldm4(al[mt], sb + SQ_WL + off);
        }
        uint32_t bh[2][2], bl[2][2];
        const int brow = ks * 16 + ln16;
        #pragma unroll
        for (int nt = 0; nt < 2; nt++) {
            uint32_t off = (uint32_t)((brow * 72 + wn * 16 + nt * 8) * 2);
            ldm2t(bh[nt], sb + SQ_XH + off);
            ldm2t(bl[nt], sb + SQ_XL + off);
        }
        #pragma unroll
        for (int mt = 0; mt < 2; mt++)
            #pragma unroll
            for (int nt = 0; nt < 2; nt++) {
                mma16816(d[mt][nt], ah[mt], bh[nt]);
                mma16816(d[mt][nt], ah[mt], bl[nt]);
                mma16816(d[mt][nt], al[mt], bh[nt]);
            }
    }
    __syncthreads();

    float* sST = (float*)(sm + SQ_ST);   // [64 o][72 j]
    #pragma unroll
    for (int mt = 0; mt < 2; mt++) {
        const int o0 = wm * 32 + mt * 16 + (lane >> 2);
        #pragma unroll
        for (int nt = 0; nt < 2; nt++) {
            const int j0 = wn * 16 + nt * 8 + (lane & 3) * 2;
            #pragma unroll
            for (int rr = 0; rr < 2; rr++) {
                const int o = o0 + rr * 8;
                sST[o * 72 + j0]     = d[mt][nt][rr * 2 + 0] + sB[o];
                sST[o * 72 + j0 + 1] = d[mt][nt][rr * 2 + 1] + sB[o];
            }
        }
    }
    __syncthreads();

    float* sNrm = (float*)(sm + SQ_NRM);
    if (tid < 128) {
        int j = tid & 63, h = tid >> 6;
        float s = 0.f;
        #pragma unroll
        for (int r = 0; r < CQ; r++) {
            float v = sST[(h * CQ + r) * 72 + j];
            s += v * v;
        }
        sNrm[tid] = rsqrtf(s);
    }
    __syncthreads();

    float* gq = g_Qn + (size_t)(b * NN + n0) * CQ;
    for (int i = tid; i < CQ * TILE; i += 256) {
        int j = i >> 5, r = i & 31;
        gq[i] = sST[r * 72 + j] * sNrm[j];
    }
    for (int i = tid; i < CQ * TILE; i += 256) {
        int r = i >> 6, j = i & 63;
        g_Kn[(size_t)(b * CQ + r) * NN + n0 + j] = sST[(CQ + r) * 72 + j] * sNrm[64 + j];
    }
}

// ---------------- kernel 2: KX = Kn_pad · x^T  (48 x 192, K = 128 per CTA) (R7 proven) ----------------
#define KX_XH 0
#define KX_XL 27648
#define KX_KH 55296
#define KX_KL 62208
#define KX_TOT 69120

__global__ __launch_bounds__(256) void kx_kernel(const float* __restrict__ x)
{
    extern __shared__ char sm[];
    const uint32_t sb = s2u(sm);
    const int tid = threadIdx.x;
    const int lane = tid & 31;
    const int wid = tid >> 5;
    const int ln16 = lane & 15;
    const int b = blockIdx.y;
    const int tile = blockIdx.x;
    const int n0 = tile * TKX;

    for (int i = tid; i < 16 * 36; i += 256) {
        int r = 32 + i / 36, jc = i % 36;
        *(uint32_t*)(sm + KX_KH + (r * 72) * 2 + jc * 4) = (r == 32 && jc < 32) ? 0x3F803F80u : 0u;
        *(uint32_t*)(sm + KX_KL + (r * 72) * 2 + jc * 4) = 0u;
    }

    float d[3][3][4];
    #pragma unroll
    for (int mt = 0; mt < 3; mt++)
        #pragma unroll
        for (int nt = 0; nt < 3; nt++)
            #pragma unroll
            for (int e = 0; e < 4; e++) d[mt][nt][e] = 0.f;

    const int n0w = wid * 24;
    for (int ch = 0; ch < TKX / 64; ch++) {
        __syncthreads();
        const float* xb = x + (size_t)b * CC * NN + n0 + ch * 64;
        for (int i = tid; i < CC * 16; i += 256) {
            int c = i >> 4, j4 = (i & 15) * 4;
            float4 v = *(const float4*)(xb + (size_t)c * NN + j4);
            uint32_t h2[2], l2[2];
            bsplit4(v, h2, l2);
            *(uint32_t*)(sm + KX_XH + (c * 72 + j4) * 2)     = h2[0];
            *(uint32_t*)(sm + KX_XH + (c * 72 + j4 + 2) * 2) = h2[1];
            *(uint32_t*)(sm + KX_XL + (c * 72 + j4) * 2)     = l2[0];
            *(uint32_t*)(sm + KX_XL + (c * 72 + j4 + 2) * 2) = l2[1];
        }
        const float* kb = g_Kn + (size_t)b * CQ * NN + n0 + ch * 64;
        for (int i = tid; i < CQ * 16; i += 256) {
            int m = i >> 4, j4 = (i & 15) * 4;
            float4 v = *(const float4*)(kb + (size_t)m * NN + j4);
            uint32_t h2[2], l2[2];
            bsplit4(v, h2, l2);
            *(uint32_t*)(sm + KX_KH + (m * 72 + j4) * 2)     = h2[0];
            *(uint32_t*)(sm + KX_KH + (m * 72 + j4 + 2) * 2) = h2[1];
            *(uint32_t*)(sm + KX_KL + (m * 72 + j4) * 2)     = l2[0];
            *(uint32_t*)(sm + KX_KL + (m * 72 + j4 + 2) * 2) = l2[1];
        }
        __syncthreads();

        #pragma unroll
        for (int ks = 0; ks < 4; ks++) {
            uint32_t ah[3][4], al[3][4];
            const int acol = ks * 16 + (lane >> 4) * 8;
            #pragma unroll
            for (int mt = 0; mt < 3; mt++) {
                uint32_t off = (uint32_t)(((mt * 16 + ln16) * 72 + acol) * 2);
                ldm4(ah[mt], sb + KX_KH + off);
                ldm4(al[mt], sb + KX_KL + off);
            }
            uint32_t bh[3][2], bl[3][2];
            #pragma unroll
            for (int nt = 0; nt < 3; nt++) {
                const int crow = n0w + nt * 8 + (lane & 7);
                const int kcol = ks * 16 + ((lane >> 3) & 1) * 8;
                uint32_t off = (uint32_t)((crow * 72 + kcol) * 2);
                ldm2(bh[nt], sb + KX_XH + off);
                ldm2(bl[nt], sb + KX_XL + off);
            }
            #pragma unroll
            for (int mt = 0; mt < 3; mt++)
                #pragma unroll
                for (int nt = 0; nt < 3; nt++) {
                    mma16816(d[mt][nt], ah[mt], bh[nt]);
                    mma16816(d[mt][nt], ah[mt], bl[nt]);
                    mma16816(d[mt][nt], al[mt], bh[nt]);
                }
        }
    }

    float* kxp = g_KXPart + (size_t)(b * NTK + tile) * (33 * CC);
    #pragma unroll
    for (int mt = 0; mt < 3; mt++) {
        const int r0 = mt * 16 + (lane >> 2);
        #pragma unroll
        for (int nt = 0; nt < 3; nt++) {
            const int c0 = n0w + nt * 8 + (lane & 3) * 2;
            #pragma unroll
            for (int rr = 0; rr < 2; rr++) {
                const int r = r0 + rr * 8;
                if (r < 33) {
                    kxp[r * CC + c0]     = d[mt][nt][rr * 2 + 0];
                    kxp[r * CC + c0 + 1] = d[mt][nt][rr * 2 + 1];
                }
            }
        }
    }
}

// ---------------- reductions (R7 proven) ----------------
__global__ __launch_bounds__(256) void ksum_kernel()
{
    const int r = blockIdx.x, b = blockIdx.y;
    const float* p = g_Kn + (size_t)(b * CQ + r) * NN;
    float s = 0.f;
    for (int i = threadIdx.x; i < NN; i += 256) s += p[i];
    __shared__ float red[256];
    red[threadIdx.x] = s;
    __syncthreads();
    for (int st = 128; st > 0; st >>= 1) {
        if (threadIdx.x < st) red[threadIdx.x] += red[threadIdx.x + st];
        __syncthreads();
    }
    if (threadIdx.x == 0) {
        g_Ksum[b * CQ + r]  = red[0];
        g_KsumE[b * CQ + r] = red[0] + 1e-6f;
    }
}

__global__ __launch_bounds__(256) void kxred_kernel()
{
    const int b = blockIdx.y;
    const int i = blockIdx.x * 256 + threadIdx.x;
    if (i >= 33 * CC) return;
    const float* p = g_KXPart + (size_t)b * NTK * (33 * CC) + i;
    float s = 0.f;
    for (int t = 0; t < NTK; t++) s += p[(size_t)t * (33 * CC)];
    g_KX[b * 33 * CC + i] = s;
}

// ---------------- tiny fp32 contraction (now emits PRE-SPLIT Mat) ----------------
#define MS_KX 0                      // [33][193] f32
#define MS_W  25476                  // [32][193] f32
#define MS_TOT 50180

__global__ __launch_bounds__(256) void matsmall_kernel(
    const float* __restrict__ Wv, const float* __restrict__ bv)
{
    extern __shared__ char sm[];
    float* sKX = (float*)(sm + MS_KX);
    float* sW  = (float*)(sm + MS_W);
    const int tid = threadIdx.x;
    const int b = blockIdx.y;
    const int c0 = blockIdx.x * 32;

    for (int i = tid; i < 33 * CC; i += 256) {
        int r = i / CC, k = i - r * CC;
        sKX[r * 193 + k] = g_KX[b * 33 * CC + i];
    }
    for (int i = tid; i < 32 * CC; i += 256) {
        int cl = i / CC, k = i - cl * CC;
        sW[cl * 193 + k] = Wv[(c0 + cl) * CC + k];
    }
    __syncthreads();

    const int m = tid >> 3, clb = (tid & 7) * 4;
    float acc[4] = {0.f, 0.f, 0.f, 0.f};
    for (int k = 0; k < CC; k++) {
        float kx = sKX[m * 193 + k];
        #pragma unroll
        for (int q = 0; q < 4; q++) acc[q] += kx * sW[(clb + q) * 193 + k];
    }
    const float ks = g_Ksum[b * CQ + m];
    #pragma unroll
    for (int q = 0; q < 4; q++) {
        int c = c0 + clb + q;
        float val = acc[q] + ks * bv[c];
        uint16_t h, l; bsplit(val, h, l);
        g_MatH[b * CQ * CC + m * CC + c] = h;
        g_MatL[b * CQ * CC + m * CC + c] = l;
    }

    if (tid < 32) {
        float vs = 0.f;
        for (int k = 0; k < CC; k++) vs += sW[tid * 193 + k] * sKX[32 * 193 + k];
        int c = c0 + tid;
        g_Vsum[b * CC + c] = vs + (float)NN * bv[c];
    }
}

// ---------------- epilogue via mma.sync: 4 tiles per CTA, pre-split Mat ----------------
#define SF_AH 0
#define SF_AL 5120
#define SF_BH 10240
#define SF_BL 23040
#define SF_ST 35840
#define SF_VS 91136
#define SF_KS 91904
#define SF_TL 92032
#define SF_TOT 92288

__global__ __launch_bounds__(256) void final_mma_kernel(
    const float* __restrict__ gamma, float* __restrict__ out)
{
    extern __shared__ char sm[];
    const uint32_t sb = s2u(sm);
    const int tid = threadIdx.x;
    const int lane = tid & 31;
    const int wid = tid >> 5;
    const int ln16 = lane & 15;
    const int b = blockIdx.y;
    const int tg = blockIdx.x;       // 4 tiles: tg*4 .. tg*4+3

    // one-time: copy pre-split Mat (pure u32 copy, no cvt), VS, KS
    const uint32_t* mh = (const uint32_t*)(g_MatH + (size_t)b * CQ * CC);
    const uint32_t* ml = (const uint32_t*)(g_MatL + (size_t)b * CQ * CC);
    for (int i = tid; i < CQ * CC / 2; i += 256) {
        int e0 = 2 * i, r = e0 / CC, c = e0 - r * CC;   // c even
        *(uint32_t*)(sm + SF_BH + (r * 200 + c) * 2) = mh[i];
        *(uint32_t*)(sm + SF_BL + (r * 200 + c) * 2) = ml[i];
    }
    float* sVS = (float*)(sm + SF_VS);
    float* sKS = (float*)(sm + SF_KS);
    float* sTL = (float*)(sm + SF_TL);
    if (tid < CC) sVS[tid] = g_Vsum[b * CC + tid];
    if (tid < CQ) sKS[tid] = g_KsumE[b * CQ + tid];

    const float g = gamma[0];
    const int wm = wid & 1, wn = wid >> 1;
    float* sST = (float*)(sm + SF_ST);   // [192][72]

    for (int t = 0; t < FTPC; t++) {
        const int n0 = (tg * FTPC + t) * TILE;
        __syncthreads();   // prev store reads done; (t=0: Mat/VS/KS writes done)

        // Qn tile -> split (float4 loads, u32 stores)
        const float* gq = g_Qn + (size_t)(b * NN + n0) * CQ;
        for (int i = tid; i < TILE * CQ / 4; i += 256) {
            int j = i >> 3, r4 = (i & 7) * 4;
            float4 v = *(const float4*)(gq + j * CQ + r4);
            uint32_t h2[2], l2[2];
            bsplit4(v, h2, l2);
            *(uint32_t*)(sm + SF_AH + (j * 40 + r4) * 2)     = h2[0];
            *(uint32_t*)(sm + SF_AH + (j * 40 + r4 + 2) * 2) = h2[1];
            *(uint32_t*)(sm + SF_AL + (j * 40 + r4) * 2)     = l2[0];
            *(uint32_t*)(sm + SF_AL + (j * 40 + r4 + 2) * 2) = l2[1];
        }
        __syncthreads();

        // tail (warps 0-1) concurrent with MMA
        if (tid < TILE) {
            float s = 0.f;
            #pragma unroll
            for (int r = 0; r < CQ; r++) {
                float q = bf16u(*(uint16_t*)(sm + SF_AH + (tid * 40 + r) * 2))
                        + bf16u(*(uint16_t*)(sm + SF_AL + (tid * 40 + r) * 2));
                s += q * sKS[r];
            }
            sTL[tid] = 1.0f / ((float)NN + s);
        }

        // D[j:64][c:192] = Qn · Mat, K=32; warp grid 2(M) x 4(N)
        float d[2][6][4];
        #pragma unroll
        for (int mt = 0; mt < 2; mt++)
            #pragma unroll
            for (int nt = 0; nt < 6; nt++)
                #pragma unroll
                for (int e = 0; e < 4; e++) d[mt][nt][e] = 0.f;

        #pragma unroll
        for (int ks = 0; ks < 2; ks++) {
            uint32_t ah[2][4], al[2][4];
            const int acol = ks * 16 + (lane >> 4) * 8;
            #pragma unroll
            for (int mt = 0; mt < 2; mt++) {
                uint32_t off = (uint32_t)(((wm * 32 + mt * 16 + ln16) * 40 + acol) * 2);
                ldm4(ah[mt], sb + SF_AH + off);
                ldm4(al[mt], sb + SF_AL + off);
            }
            uint32_t bh[6][2], bl[6][2];
            const int brow = ks * 16 + ln16;
            #pragma unroll
            for (int nt = 0; nt < 6; nt++) {
                uint32_t off = (uint32_t)((brow * 200 + wn * 48 + nt * 8) * 2);
                ldm2t(bh[nt], sb + SF_BH + off);
                ldm2t(bl[nt], sb + SF_BL + off);
            }
            #pragma unroll
            for (int mt = 0; mt < 2; mt++)
                #pragma unroll
                for (int nt = 0; nt < 6; nt++) {
                    mma16816(d[mt][nt], ah[mt], bh[nt]);
                    mma16816(d[mt][nt], ah[mt], bl[nt]);
                    mma16816(d[mt][nt], al[mt], bh[nt]);
                }
        }

        // stage transposed: sST[c][j]
        #pragma unroll
        for (int mt = 0; mt < 2; mt++) {
            const int j0 = wm * 32 + mt * 16 + (lane >> 2);
            #pragma unroll
            for (int nt = 0; nt < 6; nt++) {
                const int c0 = wn * 48 + nt * 8 + (lane & 3) * 2;
                #pragma unroll
                for (int rr = 0; rr < 2; rr++) {
                    const int j = j0 + rr * 8;
                    sST[(c0)     * 72 + j] = d[mt][nt][rr * 2 + 0];
                    sST[(c0 + 1) * 72 + j] = d[mt][nt][rr * 2 + 1];
                }
            }
        }
        __syncthreads();

        float* ob = out + (size_t)b * CC * NN + n0;
        for (int i = tid; i < CC * 16; i += 256) {
            int c = i >> 4, j4 = (i & 15) * 4;
            float4 s4 = *(const float4*)(sST + c * 72 + j4);
            float4 t4 = *(const float4*)(sTL + j4);
            float vs = sVS[c];
            float4 o4;
            o4.x = (vs + s4.x) * t4.x * g;
            o4.y = (vs + s4.y) * t4.y * g;
            o4.z = (vs + s4.z) * t4.z * g;
            o4.w = (vs + s4.w) * t4.w * g;
            *(float4*)(ob + (size_t)c * NN + j4) = o4;
        }
    }
}

// ---------------- launch ----------------
extern "C" void kernel_launch(void* const* d_in, const int* in_sizes, int n_in,
                              void* d_out, int out_size)
{
    const float* x  = (const float*)d_in[0];
    const float* x1 = (const float*)d_in[1];
    const float* Wq = (const float*)d_in[2];
    const float* bq = (const float*)d_in[3];
    const float* Wk = (const float*)d_in[4];
    const float* bk = (const float*)d_in[5];
    const float* Wv = (const float*)d_in[6];
    const float* bv = (const float*)d_in[7];
    const float* gm = (const float*)d_in[8];
    float* out = (float*)d_out;

    cudaFuncSetAttribute(qk_mma_kernel,    cudaFuncAttributeMaxDynamicSharedMemorySize, SQ_TOT);
    cudaFuncSetAttribute(kx_kernel,        cudaFuncAttributeMaxDynamicSharedMemorySize, KX_TOT);
    cudaFuncSetAttribute(matsmall_kernel,  cudaFuncAttributeMaxDynamicSharedMemorySize, MS_TOT);
    cudaFuncSetAttribute(final_mma_kernel, cudaFuncAttributeMaxDynamicSharedMemorySize, SF_TOT);

    qk_mma_kernel<<<dim3(NT, BB), 256, SQ_TOT>>>(x1, Wq, bq, Wk, bk);
    ksum_kernel<<<dim3(CQ, BB), 256>>>();
    kx_kernel<<<dim3(NTK, BB), 256, KX_TOT>>>(x);
    kxred_kernel<<<dim3((33 * CC + 255) / 256, BB), 256>>>();
    matsmall_kernel<<<dim3(6, BB), 256, MS_TOT>>>(Wv, bv);
    final_mma_kernel<<<dim3(NT / FTPC, BB), 256, SF_TOT>>>(gm, out);
}